// round 2
// baseline (speedup 1.0000x reference)
#include <cuda_runtime.h>

// MPJRDLayer fused forward.
// x:     [B=128, N=1024, D=8, S=64]  fp32   (contiguous: 512 floats per (b,n))
// W:     [N, D, S] = [1024, 512]     fp32
// theta: [N], r_hat: [N]
// out (concat): spikes [B*N], rates [N], thetas [N], r_hats [N]

#define NB   128
#define NN   1024
#define DS   512

__global__ __launch_bounds__(256, 6)
void mpjrd_fused_kernel(const float* __restrict__ x,
                        const float* __restrict__ W,
                        const float* __restrict__ theta,
                        const float* __restrict__ r_hat,
                        float* __restrict__ out)
{
    __shared__ float4 sW[DS / 4];   // 2 KB: W[n] staged once per block
    __shared__ float  scnt[8];

    const int n    = blockIdx.x;
    const int tid  = threadIdx.x;
    const int warp = tid >> 5;
    const int lane = tid & 31;

    // Stage W[n] into shared memory (coalesced float4)
    const float4* Wv = reinterpret_cast<const float4*>(W + (size_t)n * DS);
    for (int i = tid; i < DS / 4; i += 256) sW[i] = Wv[i];
    __syncthreads();

    const float th = theta[n];

    // Preload this lane's 4 W quads into registers (same for all 16 b-iters)
    float4 w0 = sW[0 * 32 + lane];
    float4 w1 = sW[1 * 32 + lane];
    float4 w2 = sW[2 * 32 + lane];
    float4 w3 = sW[3 * 32 + lane];

    float cnt = 0.0f;

    // Each warp processes 16 batch rows; x chunk per (b,n) is contiguous 2 KB.
    #pragma unroll 1
    for (int i = 0; i < 16; ++i) {
        const int b = warp * 16 + i;
        const float4* xv = reinterpret_cast<const float4*>(
            x + ((size_t)b * NN + n) * DS);

        float4 x0 = xv[0 * 32 + lane];
        float4 x1 = xv[1 * 32 + lane];
        float4 x2 = xv[2 * 32 + lane];
        float4 x3 = xv[3 * 32 + lane];

        float acc = 0.0f;
        acc = fmaf(x0.x, w0.x, acc); acc = fmaf(x0.y, w0.y, acc);
        acc = fmaf(x0.z, w0.z, acc); acc = fmaf(x0.w, w0.w, acc);
        acc = fmaf(x1.x, w1.x, acc); acc = fmaf(x1.y, w1.y, acc);
        acc = fmaf(x1.z, w1.z, acc); acc = fmaf(x1.w, w1.w, acc);
        acc = fmaf(x2.x, w2.x, acc); acc = fmaf(x2.y, w2.y, acc);
        acc = fmaf(x2.z, w2.z, acc); acc = fmaf(x2.w, w2.w, acc);
        acc = fmaf(x3.x, w3.x, acc); acc = fmaf(x3.y, w3.y, acc);
        acc = fmaf(x3.z, w3.z, acc); acc = fmaf(x3.w, w3.w, acc);

        // Warp tree-reduce
        #pragma unroll
        for (int off = 16; off; off >>= 1)
            acc += __shfl_xor_sync(0xFFFFFFFFu, acc, off);

        if (lane == 0) {
            const float s = (acc >= th) ? 1.0f : 0.0f;
            out[(size_t)b * NN + n] = s;   // spikes
            cnt += s;
        }
    }

    if (lane == 0) scnt[warp] = cnt;
    __syncthreads();

    if (tid == 0) {
        float c = 0.0f;
        #pragma unroll
        for (int w = 0; w < 8; ++w) c += scnt[w];
        const float rate = c * (1.0f / 128.0f);
        const float rh   = 0.95f * r_hat[n] + 0.05f * rate;
        const float thn  = th + 0.1f * (rh - 0.1f);
        out[NB * NN + n]            = rate;   // rates
        out[NB * NN + NN + n]       = thn;    // thetas
        out[NB * NN + 2 * NN + n]   = rh;     // r_hats
    }
}

extern "C" void kernel_launch(void* const* d_in, const int* in_sizes, int n_in,
                              void* d_out, int out_size)
{
    const float* x     = (const float*)d_in[0];
    const float* W     = (const float*)d_in[1];
    const float* theta = (const float*)d_in[2];
    const float* r_hat = (const float*)d_in[3];
    float* out = (float*)d_out;

    mpjrd_fused_kernel<<<NN, 256>>>(x, W, theta, r_hat, out);
}

// round 3
// speedup vs baseline: 1.0740x; 1.0740x over previous
#include <cuda_runtime.h>
#include <cstdint>

// MPJRDLayer fused forward — TMA-pipelined streaming version.
// x:     [B=128, N=1024, D=8, S=64] fp32 (512 contiguous floats per (b,n))
// W:     [1024, 512] fp32;  theta, r_hat: [1024]
// out:   spikes [B*N] ++ rates [N] ++ thetas [N] ++ r_hats [N]

#define NB      128
#define NN      1024
#define DS      512
#define BTILE   8                       // batch rows per pipeline stage
#define STAGES  4                       // smem ring depth
#define NSTG    (NB / BTILE)            // 16 total stages per block
#define STAGE_BYTES (BTILE * DS * 4)    // 16384
#define SMEM_X  (STAGES * STAGE_BYTES)  // 65536
#define SMEM_TOTAL (SMEM_X + 128)       // + mbarriers + warp counters

__device__ __forceinline__ uint32_t smem_u32(const void* p) {
    uint32_t a;
    asm("{ .reg .u64 t; cvta.to.shared.u64 t, %1; cvt.u32.u64 %0, t; }"
        : "=r"(a) : "l"(p));
    return a;
}

__device__ __forceinline__ void mbar_init(uint32_t mbar, uint32_t count) {
    asm volatile("mbarrier.init.shared.b64 [%0], %1;" :: "r"(mbar), "r"(count) : "memory");
}

__device__ __forceinline__ void mbar_expect_tx(uint32_t mbar, uint32_t bytes) {
    asm volatile("mbarrier.arrive.expect_tx.shared.b64 _, [%0], %1;"
                 :: "r"(mbar), "r"(bytes) : "memory");
}

__device__ __forceinline__ void bulk_g2s(uint32_t dst, const void* src,
                                         uint32_t bytes, uint32_t mbar) {
    asm volatile(
        "cp.async.bulk.shared::cluster.global.mbarrier::complete_tx::bytes "
        "[%0], [%1], %2, [%3];"
        :: "r"(dst), "l"(src), "r"(bytes), "r"(mbar) : "memory");
}

__device__ __forceinline__ void mbar_wait(uint32_t mbar, uint32_t phase) {
    asm volatile(
        "{\n\t"
        ".reg .pred P;\n\t"
        "WAIT_%=:\n\t"
        "mbarrier.try_wait.parity.acquire.cta.shared::cta.b64 P, [%0], %1, 0x989680;\n\t"
        "@P bra.uni DONE_%=;\n\t"
        "bra.uni WAIT_%=;\n\t"
        "DONE_%=:\n\t"
        "}"
        :: "r"(mbar), "r"(phase) : "memory");
}

__global__ __launch_bounds__(256)
void mpjrd_tma_kernel(const float* __restrict__ x,
                      const float* __restrict__ W,
                      const float* __restrict__ theta,
                      const float* __restrict__ r_hat,
                      float* __restrict__ out)
{
    extern __shared__ char smem[];
    float* scnt = (float*)(smem + SMEM_X + 64);        // 8 warp counters
    const uint32_t sx_base   = smem_u32(smem);
    const uint32_t mbar_base = sx_base + SMEM_X;        // 4 x 8B barriers

    const int n    = blockIdx.x;
    const int tid  = threadIdx.x;
    const int warp = tid >> 5;
    const int lane = tid & 31;

    // Init full-barriers (one arrive: the expect_tx)
    if (tid == 0) {
        #pragma unroll
        for (int s = 0; s < STAGES; ++s) mbar_init(mbar_base + 8 * s, 1);
    }
    __syncthreads();

    // Stage W[n] into per-lane registers (L2-resident: 2 MB total across grid)
    const float4* Wv = reinterpret_cast<const float4*>(W + (size_t)n * DS);
    const float4 w0 = Wv[0 * 32 + lane];
    const float4 w1 = Wv[1 * 32 + lane];
    const float4 w2 = Wv[2 * 32 + lane];
    const float4 w3 = Wv[3 * 32 + lane];
    const float  th = theta[n];

    // Prologue: fill the ring
    if (tid == 0) {
        #pragma unroll
        for (int s = 0; s < STAGES; ++s) {
            const uint32_t mb = mbar_base + 8 * s;
            mbar_expect_tx(mb, STAGE_BYTES);
            #pragma unroll
            for (int i = 0; i < BTILE; ++i) {
                const int b = s * BTILE + i;
                bulk_g2s(sx_base + s * STAGE_BYTES + i * (DS * 4),
                         x + ((size_t)b * NN + n) * DS, DS * 4, mb);
            }
        }
    }

    float cnt = 0.0f;

    for (int k = 0; k < NSTG; ++k) {
        const int      slot  = k & (STAGES - 1);
        const uint32_t phase = (k >> 2) & 1;
        mbar_wait(mbar_base + 8 * slot, phase);

        // Each warp consumes one batch row of this stage
        const int b = k * BTILE + warp;
        const float4* xs = reinterpret_cast<const float4*>(
            smem + slot * STAGE_BYTES + warp * (DS * 4));

        const float4 x0 = xs[0 * 32 + lane];
        const float4 x1 = xs[1 * 32 + lane];
        const float4 x2 = xs[2 * 32 + lane];
        const float4 x3 = xs[3 * 32 + lane];

        float acc = 0.0f;
        acc = fmaf(x0.x, w0.x, acc); acc = fmaf(x0.y, w0.y, acc);
        acc = fmaf(x0.z, w0.z, acc); acc = fmaf(x0.w, w0.w, acc);
        acc = fmaf(x1.x, w1.x, acc); acc = fmaf(x1.y, w1.y, acc);
        acc = fmaf(x1.z, w1.z, acc); acc = fmaf(x1.w, w1.w, acc);
        acc = fmaf(x2.x, w2.x, acc); acc = fmaf(x2.y, w2.y, acc);
        acc = fmaf(x2.z, w2.z, acc); acc = fmaf(x2.w, w2.w, acc);
        acc = fmaf(x3.x, w3.x, acc); acc = fmaf(x3.y, w3.y, acc);
        acc = fmaf(x3.z, w3.z, acc); acc = fmaf(x3.w, w3.w, acc);

        #pragma unroll
        for (int off = 16; off; off >>= 1)
            acc += __shfl_xor_sync(0xFFFFFFFFu, acc, off);

        if (lane == 0) {
            const float s = (acc >= th) ? 1.0f : 0.0f;
            out[(size_t)b * NN + n] = s;
            cnt += s;
        }

        // All warps done with this slot -> safe to refill
        __syncthreads();

        const int knext = k + STAGES;
        if (knext < NSTG && tid == 0) {
            const uint32_t mb = mbar_base + 8 * slot;
            mbar_expect_tx(mb, STAGE_BYTES);
            #pragma unroll
            for (int i = 0; i < BTILE; ++i) {
                const int b2 = knext * BTILE + i;
                bulk_g2s(sx_base + slot * STAGE_BYTES + i * (DS * 4),
                         x + ((size_t)b2 * NN + n) * DS, DS * 4, mb);
            }
        }
    }

    if (lane == 0) scnt[warp] = cnt;
    __syncthreads();

    if (tid == 0) {
        float c = 0.0f;
        #pragma unroll
        for (int w = 0; w < 8; ++w) c += scnt[w];
        const float rate = c * (1.0f / 128.0f);
        const float rh   = 0.95f * r_hat[n] + 0.05f * rate;
        const float thn  = th + 0.1f * (rh - 0.1f);
        out[NB * NN + n]          = rate;
        out[NB * NN + NN + n]     = thn;
        out[NB * NN + 2 * NN + n] = rh;
    }
}

extern "C" void kernel_launch(void* const* d_in, const int* in_sizes, int n_in,
                              void* d_out, int out_size)
{
    const float* x     = (const float*)d_in[0];
    const float* W     = (const float*)d_in[1];
    const float* theta = (const float*)d_in[2];
    const float* r_hat = (const float*)d_in[3];
    float* out = (float*)d_out;

    static int smem_set = 0;
    if (!smem_set) {
        cudaFuncSetAttribute(mpjrd_tma_kernel,
                             cudaFuncAttributeMaxDynamicSharedMemorySize,
                             SMEM_TOTAL);
        smem_set = 1;
    }

    mpjrd_tma_kernel<<<NN, 256, SMEM_TOTAL>>>(x, W, theta, r_hat, out);
}